// round 10
// baseline (speedup 1.0000x reference)
#include <cuda_runtime.h>
#include <cstdint>

// out[100000,128] = x[100000,128] @ (Wc+Wn)[128,128] + b[128]
// (gamma/segment-sum in the reference is dead code; edge_index unused)
//
// tf32 mma.sync (m16n8k8). CTA 128x128, 8 warps, warp tile 16x128.
// Each warp loads ITS OWN 16-row x slice via cp.async (per-warp pipeline,
// 3 stages) -> no CTA-wide barriers in the main loop. W shared in smem,
// fragment-ordered. 2 CTAs/SM.
//
// Inputs: d_in[0]=x f32 [100000,128], d_in[1]=edge_index i64 (UNUSED),
//         d_in[2]=Wc f32 [128,128], d_in[3]=Wn f32 [128,128], d_in[4]=b f32 [128]

#define D 128
#define TILE_M 128
#define KC 32
#define XW 512                   // floats per warp-stage (16 rows x 32 k)
#define XWS (3 * XW)             // per-warp x smem (3 stages)

// W fragment image: idx = (((c*4 + s)*16 + j)*32 + lane)*2 + h
//   n = j*8 + (lane>>2), k = c*32 + s*8 + (lane&3) + 4*h
__device__ float g_Wt[D * D];

__device__ __forceinline__ float to_tf32(float f) {
    float r;
    asm("cvt.rna.tf32.f32 %0, %1;" : "=f"(r) : "f"(f));
    return r;
}

__global__ void prep_w_kernel(const float* __restrict__ Wc,
                              const float* __restrict__ Wn) {
    int i = blockIdx.x * blockDim.x + threadIdx.x;
    if (i >= D * D) return;
    int h = i & 1, lane = (i >> 1) & 31, j = (i >> 6) & 15;
    int s = (i >> 10) & 3, c = i >> 12;
    int n = j * 8 + (lane >> 2);
    int k = c * 32 + s * 8 + (lane & 3) + 4 * h;
    g_Wt[i] = to_tf32(Wc[k * D + n] + Wn[k * D + n]);
}

#define MMA_TF32(c, a0, a1, a2, a3, b0, b1)                                   \
    asm volatile(                                                             \
        "mma.sync.aligned.m16n8k8.row.col.f32.tf32.tf32.f32 "                 \
        "{%0,%1,%2,%3}, {%4,%5,%6,%7}, {%8,%9}, {%0,%1,%2,%3};"               \
        : "+f"((c)[0]), "+f"((c)[1]), "+f"((c)[2]), "+f"((c)[3])              \
        : "r"(a0), "r"(a1), "r"(a2), "r"(a3), "r"(b0), "r"(b1))

__device__ __forceinline__ void cp_async16(uint32_t dst, const void* src, int valid) {
    asm volatile("cp.async.cg.shared.global [%0], [%1], 16, %2;"
                 :: "r"(dst), "l"(src), "r"(valid ? 16 : 0));
}

__global__ __launch_bounds__(256, 2)
void gemm_tf32_kernel(const float* __restrict__ x,
                      const float* __restrict__ bias,
                      float* __restrict__ out, int nrows) {
    extern __shared__ float sm[];
    float* xs = sm;                       // [8 warps][3 stages][512]
    float* ws = sm + 8 * XWS;             // [16384] frag-ordered W
    float* bias_s = ws + D * D;           // [128]

    const int tid = threadIdx.x;
    const int lane = tid & 31;
    const int wid = tid >> 5;
    const int g = lane >> 2;
    const int t4 = lane & 3;
    const int row0 = blockIdx.x * TILE_M;
    const int wrow0 = row0 + wid * 16;    // this warp's 16 rows

    const uint32_t xs_b = (uint32_t)__cvta_generic_to_shared(xs) +
                          (uint32_t)(wid * XWS) * 4;
    const uint32_t ws_b = (uint32_t)__cvta_generic_to_shared(ws);

    // per-warp x slice load (16 rows x KC), fragment-ordered:
    // 16B chunk (row, q=k>>2) -> word off ((q*2 + (row>>3))*32 + (row&7)*4)
    auto load_x_chunk = [&](int k0, int stage) {
        uint32_t xd = xs_b + (uint32_t)(stage * XW) * 4;
#pragma unroll
        for (int it = 0; it < 4; it++) {
            int ci = it * 32 + lane;          // 0..127
            int row = ci >> 3, q = ci & 7;
            int grow = wrow0 + row;
            uint32_t word = (uint32_t)(((q << 1) + (row >> 3)) * 32 + (row & 7) * 4);
            cp_async16(xd + word * 4, x + (size_t)grow * D + k0 + (q << 2),
                       grow < nrows);
        }
        asm volatile("cp.async.commit_group;" ::: "memory");
    };

    // ---- prologue: W (group 0), x0 (group 1), x1 (group 2) ----
#pragma unroll
    for (int it = 0; it < 16; it++) {
        int idx = tid + 256 * it;             // 4096 float4s of W
        cp_async16(ws_b + (uint32_t)idx * 16, g_Wt + ((size_t)idx << 2), 1);
    }
    asm volatile("cp.async.commit_group;" ::: "memory");
    if (tid < D) bias_s[tid] = bias[tid];
    load_x_chunk(0, 0);
    load_x_chunk(KC, 1);

    float acc[16][4];
#pragma unroll
    for (int j = 0; j < 16; j++)
#pragma unroll
        for (int p = 0; p < 4; p++) acc[j][p] = 0.0f;

#pragma unroll
    for (int c = 0; c < 4; c++) {
        if (c < 3)
            asm volatile("cp.async.wait_group 1;" ::: "memory");
        else
            asm volatile("cp.async.wait_group 0;" ::: "memory");
        if (c == 0)
            __syncthreads();      // W visibility across warps (once)
        else
            __syncwarp();         // own-slice visibility across lanes
        if (c + 2 < 4) load_x_chunk((c + 2) * KC, (c + 2) % 3);

        const float* xb = xs + wid * XWS + (c % 3) * XW;
        const float* wb = ws + (size_t)c * 4096 + lane * 2;

#pragma unroll
        for (int s = 0; s < 4; s++) {
            uint32_t a0 = __float_as_uint(xb[(4 * s + 0) * 32 + lane]);
            uint32_t a1 = __float_as_uint(xb[(4 * s + 1) * 32 + lane]);
            uint32_t a2 = __float_as_uint(xb[(4 * s + 2) * 32 + lane]);
            uint32_t a3 = __float_as_uint(xb[(4 * s + 3) * 32 + lane]);
            const float* wbs = wb + s * 1024;
            // two half-passes of 8 j to bound live b-registers
#pragma unroll
            for (int half = 0; half < 2; half++) {
                uint32_t b[8][2];
#pragma unroll
                for (int j = 0; j < 8; j++) {
                    float2 v = *(const float2*)(wbs + (half * 8 + j) * 64);
                    b[j][0] = __float_as_uint(v.x);
                    b[j][1] = __float_as_uint(v.y);
                }
#pragma unroll
                for (int j = 0; j < 8; j++)
                    MMA_TF32(acc[half * 8 + j], a0, a1, a2, a3, b[j][0], b[j][1]);
            }
        }
        __syncwarp();
    }

    // ---- epilogue: bias + store (rows g, g+8 of this warp's 16) ----
    const int r_lo = wrow0 + g;
    const int r_hi = r_lo + 8;
#pragma unroll
    for (int j = 0; j < 16; j++) {
        int col = 8 * j + 2 * t4;
        float2 bv = *(const float2*)(bias_s + col);
        if (r_lo < nrows) {
            float2 v = make_float2(acc[j][0] + bv.x, acc[j][1] + bv.y);
            *(float2*)(out + (size_t)r_lo * D + col) = v;
        }
        if (r_hi < nrows) {
            float2 v = make_float2(acc[j][2] + bv.x, acc[j][3] + bv.y);
            *(float2*)(out + (size_t)r_hi * D + col) = v;
        }
    }
}

extern "C" void kernel_launch(void* const* d_in, const int* in_sizes, int n_in,
                              void* d_out, int out_size) {
    const float* x    = (const float*)d_in[0];
    const float* Wc   = (const float*)d_in[2];
    const float* Wn   = (const float*)d_in[3];
    const float* bias = (const float*)d_in[4];
    float* out = (float*)d_out;

    const int nrows = in_sizes[0] / D;                 // 100000

    prep_w_kernel<<<(D * D + 255) / 256, 256>>>(Wc, Wn);

    const int smem_bytes = (8 * XWS + D * D + D) * 4;  // 115,712 B
    cudaFuncSetAttribute(gemm_tf32_kernel,
                         cudaFuncAttributeMaxDynamicSharedMemorySize, smem_bytes);

    int grid = (nrows + TILE_M - 1) / TILE_M;          // 782
    gemm_tf32_kernel<<<grid, 256, smem_bytes>>>(x, bias, out, nrows);
}

// round 12
// speedup vs baseline: 1.4528x; 1.4528x over previous
#include <cuda_runtime.h>
#include <cuda_fp16.h>
#include <cstdint>

// out[100000,128] = x[100000,128] @ (Wc+Wn)[128,128] + b[128]
// (gamma/segment-sum in the reference is dead code; edge_index unused)
//
// fp16 mma.sync (m16n8k16), f32 accum. CTA 128x128, 8 warps of 32x64, 2 CTAs/SM.
// W pre-converted to fp16 fragment order (LDS.64). x streamed as f32 via
// cp.async (3-stage pipeline), packed to fp16 in regs. Single sync per chunk.
//
// Inputs: d_in[0]=x f32 [100000,128], d_in[1]=edge_index i64 (UNUSED),
//         d_in[2]=Wc f32 [128,128], d_in[3]=Wn f32 [128,128], d_in[4]=b f32 [128]

#define D 128
#define TILE_M 128
#define KC 32
#define S40 40                    // x row stride (f32): conflict-free LDS.64 pattern
#define XST (TILE_M * S40)        // 5120 floats per x stage
#define WCH 2048                  // W words per K-chunk (128n x 32k fp16 = 8KB)

// W fp16x2 fragment image, 8192 words:
//   w = ((((c*2+wn)*2+s)*8 + j)*32 + lane)*2 + breg
//   n = wn*64 + j*8 + (lane>>2), k0 = c*32 + s*16 + breg*8 + 2*(lane&3)
//   word = half2(W[k0][n], W[k0+1][n])
__device__ uint32_t g_Wh[8192];

__global__ void prep_w_kernel(const float* __restrict__ Wc,
                              const float* __restrict__ Wn) {
    int w = blockIdx.x * blockDim.x + threadIdx.x;
    if (w >= 8192) return;
    int breg = w & 1, lane = (w >> 1) & 31, j = (w >> 6) & 7;
    int s = (w >> 9) & 1, wn = (w >> 10) & 1, c = w >> 11;
    int n = wn * 64 + j * 8 + (lane >> 2);
    int k0 = c * 32 + s * 16 + breg * 8 + 2 * (lane & 3);
    float v0 = Wc[k0 * D + n] + Wn[k0 * D + n];
    float v1 = Wc[(k0 + 1) * D + n] + Wn[(k0 + 1) * D + n];
    __half2 h = __floats2half2_rn(v0, v1);
    g_Wh[w] = *reinterpret_cast<uint32_t*>(&h);
}

#define MMA_F16(c, a0, a1, a2, a3, b0, b1)                                    \
    asm volatile(                                                             \
        "mma.sync.aligned.m16n8k16.row.col.f32.f16.f16.f32 "                  \
        "{%0,%1,%2,%3}, {%4,%5,%6,%7}, {%8,%9}, {%0,%1,%2,%3};"               \
        : "+f"((c)[0]), "+f"((c)[1]), "+f"((c)[2]), "+f"((c)[3])              \
        : "r"(a0), "r"(a1), "r"(a2), "r"(a3), "r"(b0), "r"(b1))

__device__ __forceinline__ void cp_async16(uint32_t dst, const void* src, int valid) {
    asm volatile("cp.async.cg.shared.global [%0], [%1], 16, %2;"
                 :: "r"(dst), "l"(src), "r"(valid ? 16 : 0));
}

__device__ __forceinline__ uint32_t packh2(float lo, float hi) {
    __half2 h = __floats2half2_rn(lo, hi);
    return *reinterpret_cast<uint32_t*>(&h);
}

__global__ __launch_bounds__(256, 2)
void gemm_f16_kernel(const float* __restrict__ x,
                     const float* __restrict__ bias,
                     float* __restrict__ out, int nrows) {
    extern __shared__ float sm[];
    float* xs = sm;                                   // [3][5120] f32 x stages
    uint32_t* ws = (uint32_t*)(sm + 3 * XST);         // [8192] fp16x2 W frags

    const int tid = threadIdx.x;
    const int lane = tid & 31;
    const int wid = tid >> 5;
    const int g = lane >> 2;
    const int t4 = lane & 3;
    const int wm = wid >> 1;          // 0..3 (32 rows)
    const int wn = wid & 1;           // 0..1 (64 cols)
    const int row0 = blockIdx.x * TILE_M;

    const int lr = tid >> 3;          // 0..31
    const int lj = tid & 7;           // float4 col 0..7

    const uint32_t xs_b = (uint32_t)__cvta_generic_to_shared(xs);
    const uint32_t ws_b = (uint32_t)__cvta_generic_to_shared(ws);

    auto load_x_chunk = [&](int k0, int buf) {
        uint32_t xd = xs_b + (uint32_t)(buf * XST) * 4;
#pragma unroll
        for (int it = 0; it < 4; it++) {
            int r = lr + 32 * it;
            int grow = row0 + r;
            cp_async16(xd + (uint32_t)(r * S40 + lj * 4) * 4,
                       x + (size_t)grow * D + k0 + lj * 4, grow < nrows);
        }
        asm volatile("cp.async.commit_group;" ::: "memory");
    };

    // ---- prologue: W (group 0) | x0 | x1 ----
#pragma unroll
    for (int it = 0; it < 8; it++) {            // 2048 float4s of W (32KB)
        int idx = tid + 256 * it;
        cp_async16(ws_b + (uint32_t)idx * 16, g_Wh + ((size_t)idx << 2), 1);
    }
    asm volatile("cp.async.commit_group;" ::: "memory");
    load_x_chunk(0, 0);
    load_x_chunk(KC, 1);

    float acc[2][8][4];
#pragma unroll
    for (int i = 0; i < 2; i++)
#pragma unroll
        for (int j = 0; j < 8; j++)
#pragma unroll
            for (int p = 0; p < 4; p++) acc[i][j][p] = 0.0f;

    // base: + wn*1024 + lane*2; chunk stride WCH=2048, s stride 512, j stride 64
    const uint32_t* wb_base = ws + wn * 1024 + lane * 2;

#pragma unroll
    for (int c = 0; c < 4; c++) {
        if (c < 3)
            asm volatile("cp.async.wait_group 1;" ::: "memory");
        else
            asm volatile("cp.async.wait_group 0;" ::: "memory");
        __syncthreads();
        if (c + 2 < 4) load_x_chunk((c + 2) * KC, (c + 2) % 3);

        const float* xb = xs + (c % 3) * XST;
        const uint32_t* wc = wb_base + c * WCH;

#pragma unroll
        for (int s = 0; s < 2; s++) {
            // b fragments: 8 x LDS.64, conflict-free (half-warp covers 32 banks)
            uint32_t b[8][2];
#pragma unroll
            for (int j = 0; j < 8; j++) {
                uint2 v = *(const uint2*)(wc + s * 512 + j * 64);
                b[j][0] = v.x;
                b[j][1] = v.y;
            }
#pragma unroll
            for (int i = 0; i < 2; i++) {
                const float* xr = xb + (wm * 32 + i * 16 + g) * S40 + s * 16 + 2 * t4;
                float2 v0 = *(const float2*)(xr);               // row g,   k 2t4
                float2 v1 = *(const float2*)(xr + 8 * S40);     // row g+8, k 2t4
                float2 v2 = *(const float2*)(xr + 8);           // row g,   k 2t4+8
                float2 v3 = *(const float2*)(xr + 8 * S40 + 8); // row g+8, k 2t4+8
                uint32_t a0 = packh2(v0.x, v0.y);
                uint32_t a1 = packh2(v1.x, v1.y);
                uint32_t a2 = packh2(v2.x, v2.y);
                uint32_t a3 = packh2(v3.x, v3.y);
#pragma unroll
                for (int j = 0; j < 8; j++)
                    MMA_F16(acc[i][j], a0, a1, a2, a3, b[j][0], b[j][1]);
            }
        }
    }

    // ---- epilogue: bias + store directly from accumulators ----
#pragma unroll
    for (int j = 0; j < 8; j++) {
        int col = wn * 64 + 8 * j + 2 * t4;
        float b0 = __ldg(bias + col), b1 = __ldg(bias + col + 1);
#pragma unroll
        for (int i = 0; i < 2; i++) {
            int r_lo = row0 + wm * 32 + 16 * i + g;
            int r_hi = r_lo + 8;
            if (r_lo < nrows) {
                float2 v = make_float2(acc[i][j][0] + b0, acc[i][j][1] + b1);
                *(float2*)(out + (size_t)r_lo * D + col) = v;
            }
            if (r_hi < nrows) {
                float2 v = make_float2(acc[i][j][2] + b0, acc[i][j][3] + b1);
                *(float2*)(out + (size_t)r_hi * D + col) = v;
            }
        }
    }
}

extern "C" void kernel_launch(void* const* d_in, const int* in_sizes, int n_in,
                              void* d_out, int out_size) {
    const float* x    = (const float*)d_in[0];
    const float* Wc   = (const float*)d_in[2];
    const float* Wn   = (const float*)d_in[3];
    const float* bias = (const float*)d_in[4];
    float* out = (float*)d_out;

    const int nrows = in_sizes[0] / D;                 // 100000

    prep_w_kernel<<<32, 256>>>(Wc, Wn);

    const int smem_bytes = (3 * XST + 8192) * 4;       // 94,208 B
    cudaFuncSetAttribute(gemm_f16_kernel,
                         cudaFuncAttributeMaxDynamicSharedMemorySize, smem_bytes);

    int grid = (nrows + TILE_M - 1) / TILE_M;          // 782
    gemm_f16_kernel<<<grid, 256, smem_bytes>>>(x, bias, out, nrows);
}

// round 13
// speedup vs baseline: 1.5714x; 1.0816x over previous
#include <cuda_runtime.h>
#include <cuda_fp16.h>
#include <cstdint>

// out[100000,128] = x[100000,128] @ (Wc+Wn)[128,128] + b[128]
// (gamma/segment-sum in the reference is dead code; edge_index unused)
//
// fp16 mma.sync (m16n8k16), f32 accum. CTA 128x128, 8 warps of 32x64.
// Warp PAIRS {2p,2p+1} share a 32-row x slice: each pair loads its own slice
// (cp.async, 3-stage pipeline) and syncs with a 64-thread named barrier --
// no CTA-wide barrier in the chunk loop (only one for W at chunk 0).
//
// Inputs: d_in[0]=x f32 [100000,128], d_in[1]=edge_index i64 (UNUSED),
//         d_in[2]=Wc f32 [128,128], d_in[3]=Wn f32 [128,128], d_in[4]=b f32 [128]

#define D 128
#define TILE_M 128
#define KC 32
#define S40 40                    // x row stride (f32): conflict-free LDS.64
#define XWS (32 * S40)            // 1280 floats per pair-stage (32 rows x 32 k)
#define WCH 2048                  // W words per K-chunk (128n x 32k fp16)

// W fp16x2 fragment image, 8192 words:
//   w = ((((c*2+wn)*2+s)*8 + j)*32 + lane)*2 + breg
//   n = wn*64 + j*8 + (lane>>2), k0 = c*32 + s*16 + breg*8 + 2*(lane&3)
__device__ uint32_t g_Wh[8192];

__global__ void prep_w_kernel(const float* __restrict__ Wc,
                              const float* __restrict__ Wn) {
    int w = blockIdx.x * blockDim.x + threadIdx.x;
    if (w >= 8192) return;
    int breg = w & 1, lane = (w >> 1) & 31, j = (w >> 6) & 7;
    int s = (w >> 9) & 1, wn = (w >> 10) & 1, c = w >> 11;
    int n = wn * 64 + j * 8 + (lane >> 2);
    int k0 = c * 32 + s * 16 + breg * 8 + 2 * (lane & 3);
    float v0 = Wc[k0 * D + n] + Wn[k0 * D + n];
    float v1 = Wc[(k0 + 1) * D + n] + Wn[(k0 + 1) * D + n];
    __half2 h = __floats2half2_rn(v0, v1);
    g_Wh[w] = *reinterpret_cast<uint32_t*>(&h);
}

#define MMA_F16(c, a0, a1, a2, a3, b0, b1)                                    \
    asm volatile(                                                             \
        "mma.sync.aligned.m16n8k16.row.col.f32.f16.f16.f32 "                  \
        "{%0,%1,%2,%3}, {%4,%5,%6,%7}, {%8,%9}, {%0,%1,%2,%3};"               \
        : "+f"((c)[0]), "+f"((c)[1]), "+f"((c)[2]), "+f"((c)[3])              \
        : "r"(a0), "r"(a1), "r"(a2), "r"(a3), "r"(b0), "r"(b1))

__device__ __forceinline__ void cp_async16(uint32_t dst, const void* src, int valid) {
    asm volatile("cp.async.cg.shared.global [%0], [%1], 16, %2;"
                 :: "r"(dst), "l"(src), "r"(valid ? 16 : 0));
}

__device__ __forceinline__ uint32_t packh2(float lo, float hi) {
    __half2 h = __floats2half2_rn(lo, hi);
    return *reinterpret_cast<uint32_t*>(&h);
}

__global__ __launch_bounds__(256, 2)
void gemm_f16_kernel(const float* __restrict__ x,
                     const float* __restrict__ bias,
                     float* __restrict__ out, int nrows) {
    extern __shared__ float sm[];
    float* xs = sm;                                   // [4 pairs][3 stages][1280]
    uint32_t* ws = (uint32_t*)(sm + 12 * XWS);        // [8192] fp16x2 W frags

    const int tid = threadIdx.x;
    const int lane = tid & 31;
    const int wid = tid >> 5;
    const int g = lane >> 2;
    const int t4 = lane & 3;
    const int wm = wid >> 1;          // 0..3 = pair id (32 rows each)
    const int wn = wid & 1;           // 0..1 (64 cols)
    const int row0 = blockIdx.x * TILE_M;
    const int prow0 = row0 + wm * 32; // pair's first row

    const int ptid = tid & 63;        // thread within pair
    const int plr = ptid >> 3;        // 0..7 (row block base)
    const int plj = ptid & 7;         // float4 col 0..7

    const uint32_t xs_b = (uint32_t)__cvta_generic_to_shared(xs) +
                          (uint32_t)(wm * 3 * XWS) * 4;
    const uint32_t ws_b = (uint32_t)__cvta_generic_to_shared(ws);

    // pair-local x slice load: 32 rows x 32 k = 256 float4, 64 threads, 4 each
    auto load_x_chunk = [&](int k0, int stage) {
        uint32_t xd = xs_b + (uint32_t)(stage * XWS) * 4;
#pragma unroll
        for (int it = 0; it < 4; it++) {
            int r = plr + 8 * it;                 // 0..31
            int grow = prow0 + r;
            cp_async16(xd + (uint32_t)(r * S40 + plj * 4) * 4,
                       x + (size_t)grow * D + k0 + plj * 4, grow < nrows);
        }
        asm volatile("cp.async.commit_group;" ::: "memory");
    };

    // ---- prologue: W (group 0) | x0 | x1 ----
#pragma unroll
    for (int it = 0; it < 8; it++) {              // 2048 float4s of W (32KB)
        int idx = tid + 256 * it;
        cp_async16(ws_b + (uint32_t)idx * 16, g_Wh + ((size_t)idx << 2), 1);
    }
    asm volatile("cp.async.commit_group;" ::: "memory");
    load_x_chunk(0, 0);
    load_x_chunk(KC, 1);

    float acc[2][8][4];
#pragma unroll
    for (int i = 0; i < 2; i++)
#pragma unroll
        for (int j = 0; j < 8; j++)
#pragma unroll
            for (int p = 0; p < 4; p++) acc[i][j][p] = 0.0f;

    const uint32_t* wb_base = ws + wn * 1024 + lane * 2;
    const int barid = wm + 1;

#pragma unroll
    for (int c = 0; c < 4; c++) {
        if (c < 3)
            asm volatile("cp.async.wait_group 1;" ::: "memory");
        else
            asm volatile("cp.async.wait_group 0;" ::: "memory");
        if (c == 0)
            __syncthreads();                       // W + x0 visible CTA-wide
        else
            asm volatile("bar.sync %0, 64;" :: "r"(barid) : "memory");
        if (c + 2 < 4) load_x_chunk((c + 2) * KC, (c + 2) % 3);

        const float* xb = xs + (wm * 3 + (c % 3)) * XWS;
        const uint32_t* wc = wb_base + c * WCH;

#pragma unroll
        for (int s = 0; s < 2; s++) {
            uint32_t b[8][2];
#pragma unroll
            for (int j = 0; j < 8; j++) {
                uint2 v = *(const uint2*)(wc + s * 512 + j * 64);
                b[j][0] = v.x;
                b[j][1] = v.y;
            }
#pragma unroll
            for (int i = 0; i < 2; i++) {
                const float* xr = xb + (i * 16 + g) * S40 + s * 16 + 2 * t4;
                float2 v0 = *(const float2*)(xr);               // row g,   k 2t4
                float2 v1 = *(const float2*)(xr + 8 * S40);     // row g+8
                float2 v2 = *(const float2*)(xr + 8);           // k 2t4+8
                float2 v3 = *(const float2*)(xr + 8 * S40 + 8);
                uint32_t a0 = packh2(v0.x, v0.y);
                uint32_t a1 = packh2(v1.x, v1.y);
                uint32_t a2 = packh2(v2.x, v2.y);
                uint32_t a3 = packh2(v3.x, v3.y);
#pragma unroll
                for (int j = 0; j < 8; j++)
                    MMA_F16(acc[i][j], a0, a1, a2, a3, b[j][0], b[j][1]);
            }
        }
    }

    // ---- epilogue: bias + store directly from accumulators ----
#pragma unroll
    for (int j = 0; j < 8; j++) {
        int col = wn * 64 + 8 * j + 2 * t4;
        float b0 = __ldg(bias + col), b1 = __ldg(bias + col + 1);
#pragma unroll
        for (int i = 0; i < 2; i++) {
            int r_lo = prow0 + 16 * i + g;
            int r_hi = r_lo + 8;
            if (r_lo < nrows) {
                float2 v = make_float2(acc[i][j][0] + b0, acc[i][j][1] + b1);
                *(float2*)(out + (size_t)r_lo * D + col) = v;
            }
            if (r_hi < nrows) {
                float2 v = make_float2(acc[i][j][2] + b0, acc[i][j][3] + b1);
                *(float2*)(out + (size_t)r_hi * D + col) = v;
            }
        }
    }
}

extern "C" void kernel_launch(void* const* d_in, const int* in_sizes, int n_in,
                              void* d_out, int out_size) {
    const float* x    = (const float*)d_in[0];
    const float* Wc   = (const float*)d_in[2];
    const float* Wn   = (const float*)d_in[3];
    const float* bias = (const float*)d_in[4];
    float* out = (float*)d_out;

    const int nrows = in_sizes[0] / D;                 // 100000

    prep_w_kernel<<<32, 256>>>(Wc, Wn);

    const int smem_bytes = (12 * XWS + 8192) * 4;      // 94,208 B
    cudaFuncSetAttribute(gemm_f16_kernel,
                         cudaFuncAttributeMaxDynamicSharedMemorySize, smem_bytes);

    int grid = (nrows + TILE_M - 1) / TILE_M;          // 782
    gemm_f16_kernel<<<grid, 256, smem_bytes>>>(x, bias, out, nrows);
}